// round 9
// baseline (speedup 1.0000x reference)
#include <cuda_runtime.h>
#include <cuda_bf16.h>
#include <cstdint>

#define NN   8192
#define IND  128
#define OUTD 64
#define NSPLIT 8
#define JCHUNK (NN / NSPLIT)   // 1024 j per split
#define JT 32                  // K tile
#define ITILE 128              // M rows per block
#define NTILES (JCHUNK / JT)   // 32

// swizzled tiles: row stride 32 bf16 (64B), chunk(16B) ^= s(row), s=(r^(r>>2))&3
// smem elem offsets (bf16), double buffered
#define OFF_AH(b) ((b) * 4096)
#define OFF_AL(b) (8192 + (b) * 4096)
#define OFF_BH(b) (16384 + (b) * 2048)
#define OFF_BL(b) (20480 + (b) * 2048)
#define OFF_S2   24576                  // float s2 segment: 1024 floats = 2048 elem-slots
#define SMEM_ELEMS (24576 + 2048)
#define SMEM_BYTES (SMEM_ELEMS * 2)     // 53248 B

// static device scratch (no allocations allowed)
__device__ float g_Wh[(size_t)NN * OUTD];
__device__ float g_s1[NN];
__device__ float g_s2[NN];
__device__ __nv_bfloat16 g_WhT_hi[(size_t)OUTD * NN];  // [d][j]
__device__ __nv_bfloat16 g_WhT_lo[(size_t)OUTD * NN];
__device__ float g_part[(size_t)NSPLIT * NN * OUTD];
__device__ float g_lp[(size_t)NSPLIT * NN];

__device__ __forceinline__ uint32_t smem_u32(const void* p) {
    return (uint32_t)__cvta_generic_to_shared(p);
}
__device__ __forceinline__ void ldsm_x4(uint32_t& r0, uint32_t& r1, uint32_t& r2, uint32_t& r3, uint32_t a) {
    asm volatile("ldmatrix.sync.aligned.m8n8.x4.shared.b16 {%0,%1,%2,%3}, [%4];"
                 : "=r"(r0), "=r"(r1), "=r"(r2), "=r"(r3) : "r"(a));
}
__device__ __forceinline__ void mma_bf16(float* c, const uint32_t* A, uint32_t b0, uint32_t b1) {
    asm volatile(
        "mma.sync.aligned.m16n8k16.row.col.f32.bf16.bf16.f32 "
        "{%0,%1,%2,%3}, {%4,%5,%6,%7}, {%8,%9}, {%0,%1,%2,%3};"
        : "+f"(c[0]), "+f"(c[1]), "+f"(c[2]), "+f"(c[3])
        : "r"(A[0]), "r"(A[1]), "r"(A[2]), "r"(A[3]), "r"(b0), "r"(b1));
}
__device__ __forceinline__ int swz(int row) { return (row ^ (row >> 2)) & 3; }

// ---------------------------------------------------------------------------
// K1: Wh = x@W (fp32, coalesced); s1/s2 = Wh@a halves
// ---------------------------------------------------------------------------
__global__ __launch_bounds__(128) void k1_proj(const float* __restrict__ x,
                                               const float* __restrict__ W,
                                               const float* __restrict__ a) {
    __shared__ float W_sm[IND][OUTD];
    __shared__ float x_sm[32][33];

    const int t  = threadIdx.x;
    const int i0 = blockIdx.x * 32;
    const int dl = t & 15;
    const int rl = t >> 4;

    {
        const float4* src = (const float4*)W;
        float4* dst = (float4*)&W_sm[0][0];
#pragma unroll
        for (int q = 0; q < 16; ++q) dst[t + 128 * q] = src[t + 128 * q];
    }

    float acc[4][4];
#pragma unroll
    for (int rr = 0; rr < 4; ++rr)
#pragma unroll
        for (int dd = 0; dd < 4; ++dd) acc[rr][dd] = 0.f;

    for (int k0 = 0; k0 < IND; k0 += 32) {
        __syncthreads();
#pragma unroll
        for (int q = 0; q < 8; ++q) {
            int idx = t + 128 * q;
            int r = idx >> 5, kk = idx & 31;
            x_sm[r][kk] = x[(size_t)(i0 + r) * IND + k0 + kk];
        }
        __syncthreads();
#pragma unroll
        for (int kk = 0; kk < 32; ++kk) {
            float4 w = *(const float4*)&W_sm[k0 + kk][dl * 4];
#pragma unroll
            for (int rr = 0; rr < 4; ++rr) {
                float xv = x_sm[rl * 4 + rr][kk];
                acc[rr][0] += xv * w.x;
                acc[rr][1] += xv * w.y;
                acc[rr][2] += xv * w.z;
                acc[rr][3] += xv * w.w;
            }
        }
    }

    const float* a1 = a;
    const float* a2 = a + OUTD;
#pragma unroll
    for (int rr = 0; rr < 4; ++rr) {
        int row = i0 + rl * 4 + rr;
        *(float4*)&g_Wh[(size_t)row * OUTD + dl * 4] =
            make_float4(acc[rr][0], acc[rr][1], acc[rr][2], acc[rr][3]);
        float4 av1 = *(const float4*)&a1[dl * 4];
        float4 av2 = *(const float4*)&a2[dl * 4];
        float v1 = acc[rr][0] * av1.x + acc[rr][1] * av1.y + acc[rr][2] * av1.z + acc[rr][3] * av1.w;
        float v2 = acc[rr][0] * av2.x + acc[rr][1] * av2.y + acc[rr][2] * av2.z + acc[rr][3] * av2.w;
#pragma unroll
        for (int o = 8; o >= 1; o >>= 1) {
            v1 += __shfl_xor_sync(0xffffffffu, v1, o, 16);
            v2 += __shfl_xor_sync(0xffffffffu, v2, o, 16);
        }
        if (dl == 0) { g_s1[row] = v1; g_s2[row] = v2; }
    }
}

// ---------------------------------------------------------------------------
// K1b: transpose Wh -> WhT hi/lo bf16
// ---------------------------------------------------------------------------
__global__ __launch_bounds__(256) void k1b_transpose() {
    __shared__ float ts[64][68];
    const int t  = threadIdx.x;
    const int j0 = blockIdx.x * 64;

#pragma unroll
    for (int q = 0; q < 4; ++q) {
        int idx = t + 256 * q;
        int r = idx >> 4, c4 = (idx & 15) * 4;
        *(float4*)&ts[r][c4] = *(const float4*)&g_Wh[(size_t)(j0 + r) * OUTD + c4];
    }
    __syncthreads();

    const int d  = t >> 2;
    const int jq = (t & 3) * 16;
    uint32_t hi[8], lo[8];
#pragma unroll
    for (int u = 0; u < 8; ++u) {
        float v0 = ts[jq + 2 * u][d];
        float v1 = ts[jq + 2 * u + 1][d];
        __nv_bfloat162 h = __float22bfloat162_rn(make_float2(v0, v1));
        uint32_t uh = *(uint32_t*)&h;
        hi[u] = uh;
        float r0 = v0 - __uint_as_float(uh << 16);
        float r1 = v1 - __uint_as_float(uh & 0xffff0000u);
        __nv_bfloat162 l = __float22bfloat162_rn(make_float2(r0, r1));
        lo[u] = *(uint32_t*)&l;
    }
    __nv_bfloat16* dh = g_WhT_hi + (size_t)d * NN + j0 + jq;
    __nv_bfloat16* dl = g_WhT_lo + (size_t)d * NN + j0 + jq;
    *(uint4*)dh       = make_uint4(hi[0], hi[1], hi[2], hi[3]);
    *(uint4*)(dh + 8) = make_uint4(hi[4], hi[5], hi[6], hi[7]);
    *(uint4*)dl       = make_uint4(lo[0], lo[1], lo[2], lo[3]);
    *(uint4*)(dl + 8) = make_uint4(lo[4], lo[5], lo[6], lo[7]);
}

// ---------------------------------------------------------------------------
// K2: software-pipelined, swizzled smem, 4 blocks/SM (single wave).
// ---------------------------------------------------------------------------
__global__ __launch_bounds__(128, 4) void k2_attn_mma(const int* __restrict__ adj) {
    extern __shared__ __nv_bfloat16 sm[];
    float* s2s = (float*)(sm + OFF_S2);

    const int t     = threadIdx.x;
    const int wid   = t >> 5;
    const int lid   = t & 31;
    const int i0    = blockIdx.x * ITILE;
    const int split = blockIdx.y;
    const int js    = split * JCHUNK;

    const float s1v = g_s1[i0 + t];
    const int* adjrow = adj + (size_t)(i0 + t) * NN + js;
    const int bn = t >> 1, bklc = (t & 1) * 2;   // B-phase: row bn, logical chunks bklc, bklc+1
    const int sBw = swz(bn);
    const __nv_bfloat16* bhp = g_WhT_hi + (size_t)bn * NN + js + (t & 1) * 16;
    const __nv_bfloat16* blp = g_WhT_lo + (size_t)bn * NN + js + (t & 1) * 16;
    const int sAw = swz(t);                      // A-phase write swizzle (row t)

    // preload s2 segment (1024 floats) into smem
#pragma unroll
    for (int q = 0; q < 2; ++q)
        *(float4*)&s2s[t * 8 + 4 * q] = *(const float4*)&g_s2[js + t * 8 + 4 * q];

    float lacc = 0.f;
    float c[2][8][4];
#pragma unroll
    for (int mt = 0; mt < 2; ++mt)
#pragma unroll
        for (int nt = 0; nt < 8; ++nt)
#pragma unroll
            for (int q = 0; q < 4; ++q) c[mt][nt][q] = 0.f;

    auto build = [&](int tl, int b, const int4* pa) {
        const int j0 = tl * JT;
        // B tile
        {
            const __nv_bfloat16* sh = bhp + j0;
            const __nv_bfloat16* sl = blp + j0;
            __nv_bfloat16* Bh = sm + OFF_BH(b) + bn * 32;
            __nv_bfloat16* Bl = sm + OFF_BL(b) + bn * 32;
            *(uint4*)(Bh + (((bklc + 0) ^ sBw) << 3)) = *(const uint4*)sh;
            *(uint4*)(Bh + (((bklc + 1) ^ sBw) << 3)) = *(const uint4*)(sh + 8);
            *(uint4*)(Bl + (((bklc + 0) ^ sBw) << 3)) = *(const uint4*)sl;
            *(uint4*)(Bl + (((bklc + 1) ^ sBw) << 3)) = *(const uint4*)(sl + 8);
        }
        // A tile: thread t computes 32 p values for row t
        const float4* s4p = (const float4*)(s2s + j0);
        __nv_bfloat16* Ah = sm + OFF_AH(b) + t * 32;
        __nv_bfloat16* Al = sm + OFF_AL(b) + t * 32;
#pragma unroll
        for (int k = 0; k < 4; ++k) {
            int4   aA = pa[2 * k], aB = pa[2 * k + 1];
            float4 sA = s4p[2 * k], sB = s4p[2 * k + 1];
            float p0, p1, p2, p3, p4, p5, p6, p7, e;
            e = s1v + sA.x; e = fmaxf(e, 0.2f * e); p0 = aA.x ? __expf(e) : 0.f;
            e = s1v + sA.y; e = fmaxf(e, 0.2f * e); p1 = aA.y ? __expf(e) : 0.f;
            e = s1v + sA.z; e = fmaxf(e, 0.2f * e); p2 = aA.z ? __expf(e) : 0.f;
            e = s1v + sA.w; e = fmaxf(e, 0.2f * e); p3 = aA.w ? __expf(e) : 0.f;
            e = s1v + sB.x; e = fmaxf(e, 0.2f * e); p4 = aB.x ? __expf(e) : 0.f;
            e = s1v + sB.y; e = fmaxf(e, 0.2f * e); p5 = aB.y ? __expf(e) : 0.f;
            e = s1v + sB.z; e = fmaxf(e, 0.2f * e); p6 = aB.z ? __expf(e) : 0.f;
            e = s1v + sB.w; e = fmaxf(e, 0.2f * e); p7 = aB.w ? __expf(e) : 0.f;
            lacc += ((p0 + p1) + (p2 + p3)) + ((p4 + p5) + (p6 + p7));

            __nv_bfloat162 h01 = __float22bfloat162_rn(make_float2(p0, p1));
            __nv_bfloat162 h23 = __float22bfloat162_rn(make_float2(p2, p3));
            __nv_bfloat162 h45 = __float22bfloat162_rn(make_float2(p4, p5));
            __nv_bfloat162 h67 = __float22bfloat162_rn(make_float2(p6, p7));
            uint32_t u01 = *(uint32_t*)&h01, u23 = *(uint32_t*)&h23;
            uint32_t u45 = *(uint32_t*)&h45, u67 = *(uint32_t*)&h67;
            *(uint4*)(Ah + ((k ^ sAw) << 3)) = make_uint4(u01, u23, u45, u67);

            float l0 = p0 - __uint_as_float(u01 << 16);
            float l1 = p1 - __uint_as_float(u01 & 0xffff0000u);
            float l2 = p2 - __uint_as_float(u23 << 16);
            float l3 = p3 - __uint_as_float(u23 & 0xffff0000u);
            float l4 = p4 - __uint_as_float(u45 << 16);
            float l5 = p5 - __uint_as_float(u45 & 0xffff0000u);
            float l6 = p6 - __uint_as_float(u67 << 16);
            float l7 = p7 - __uint_as_float(u67 & 0xffff0000u);
            __nv_bfloat162 q01 = __float22bfloat162_rn(make_float2(l0, l1));
            __nv_bfloat162 q23 = __float22bfloat162_rn(make_float2(l2, l3));
            __nv_bfloat162 q45 = __float22bfloat162_rn(make_float2(l4, l5));
            __nv_bfloat162 q67 = __float22bfloat162_rn(make_float2(l6, l7));
            *(uint4*)(Al + ((k ^ sAw) << 3)) = make_uint4(*(uint32_t*)&q01, *(uint32_t*)&q23,
                                                          *(uint32_t*)&q45, *(uint32_t*)&q67);
        }
    };

    // MMA lane roles
    const int arow  = wid * 32 + (lid & 15);   // + mt*16
    const int ahc   = lid >> 4;                // A k-half chunk bit
    const int sAr   = swz(arow);               // invariant under +16
    const int bnl   = (lid & 7) + ((lid >> 4) << 3);   // + np*16
    const int bhc   = (lid >> 3) & 1;
    const int sBr   = swz(bnl);

    // prologue
    {
        int4 pa[8];
#pragma unroll
        for (int q = 0; q < 8; ++q) pa[q] = ((const int4*)adjrow)[q];
        __syncthreads();   // s2s ready
        build(0, 0, pa);
    }
    __syncthreads();

    for (int tile = 0; tile < NTILES; ++tile) {
        const int cur = tile & 1, nb = cur ^ 1;

        int4 pa[8];
        if (tile + 1 < NTILES) {
            const int4* src = (const int4*)(adjrow + (tile + 1) * JT);
#pragma unroll
            for (int q = 0; q < 8; ++q) pa[q] = src[q];
        }

        // ---- MMA on buffer cur
#pragma unroll
        for (int kt = 0; kt < 2; ++kt) {
            uint32_t Ah[2][4], Al[2][4];
#pragma unroll
            for (int mt = 0; mt < 2; ++mt) {
                uint32_t aoff = (uint32_t)((arow + mt * 16) * 32 + ((((kt << 1) | ahc) ^ sAr) << 3));
                ldsm_x4(Ah[mt][0], Ah[mt][1], Ah[mt][2], Ah[mt][3], smem_u32(sm + OFF_AH(cur) + aoff));
                ldsm_x4(Al[mt][0], Al[mt][1], Al[mt][2], Al[mt][3], smem_u32(sm + OFF_AL(cur) + aoff));
            }
#pragma unroll
            for (int np = 0; np < 4; ++np) {
                uint32_t boff = (uint32_t)((bnl + np * 16) * 32 + ((((kt << 1) | bhc) ^ sBr) << 3));
                uint32_t bh0, bh1, bh2, bh3, bl0, bl1, bl2, bl3;
                ldsm_x4(bh0, bh1, bh2, bh3, smem_u32(sm + OFF_BH(cur) + boff));
                ldsm_x4(bl0, bl1, bl2, bl3, smem_u32(sm + OFF_BL(cur) + boff));
#pragma unroll
                for (int mt = 0; mt < 2; ++mt) {
                    mma_bf16(c[mt][2 * np],     Ah[mt], bh0, bh1);
                    mma_bf16(c[mt][2 * np],     Ah[mt], bl0, bl1);
                    mma_bf16(c[mt][2 * np],     Al[mt], bh0, bh1);
                    mma_bf16(c[mt][2 * np + 1], Ah[mt], bh2, bh3);
                    mma_bf16(c[mt][2 * np + 1], Ah[mt], bl2, bl3);
                    mma_bf16(c[mt][2 * np + 1], Al[mt], bh2, bh3);
                }
            }
        }

        if (tile + 1 < NTILES) build(tile + 1, nb, pa);
        __syncthreads();
    }

    g_lp[(size_t)split * NN + i0 + t] = lacc;

    // ---- epilogue: raw partials
    const int rbase = i0 + wid * 32 + (lid >> 2);
    const int cbase = 2 * (lid & 3);
#pragma unroll
    for (int mt = 0; mt < 2; ++mt) {
#pragma unroll
        for (int nt = 0; nt < 8; ++nt) {
            const int col = nt * 8 + cbase;
            float* d0 = &g_part[((size_t)split * NN + rbase + mt * 16) * OUTD + col];
            float* d1 = &g_part[((size_t)split * NN + rbase + mt * 16 + 8) * OUTD + col];
            *(float2*)d0 = make_float2(c[mt][nt][0], c[mt][nt][1]);
            *(float2*)d1 = make_float2(c[mt][nt][2], c[mt][nt][3]);
        }
    }
}

// ---------------------------------------------------------------------------
// K3: reduce NSPLIT partials, normalize, ELU.
// ---------------------------------------------------------------------------
__global__ __launch_bounds__(128) void k3_reduce(float* __restrict__ out) {
    const int q   = blockIdx.x * 128 + threadIdx.x;
    const int row = q >> 4;
    const int c4  = (q & 15) * 4;

    float l = 0.f;
#pragma unroll
    for (int s = 0; s < NSPLIT; ++s) l += g_lp[(size_t)s * NN + row];
    const float inv = 1.0f / l;

    float4 acc = make_float4(0.f, 0.f, 0.f, 0.f);
#pragma unroll
    for (int s = 0; s < NSPLIT; ++s) {
        float4 v = *(const float4*)&g_part[((size_t)s * NN + row) * OUTD + c4];
        acc.x += v.x; acc.y += v.y; acc.z += v.z; acc.w += v.w;
    }
    acc.x *= inv; acc.y *= inv; acc.z *= inv; acc.w *= inv;
    acc.x = acc.x > 0.f ? acc.x : expm1f(acc.x);
    acc.y = acc.y > 0.f ? acc.y : expm1f(acc.y);
    acc.z = acc.z > 0.f ? acc.z : expm1f(acc.z);
    acc.w = acc.w > 0.f ? acc.w : expm1f(acc.w);
    *(float4*)&out[(size_t)row * OUTD + c4] = acc;
}

extern "C" void kernel_launch(void* const* d_in, const int* in_sizes, int n_in,
                              void* d_out, int out_size) {
    const float* x   = (const float*)d_in[0];
    const int*   adj = (const int*)d_in[1];
    const float* W   = (const float*)d_in[2];
    const float* a   = (const float*)d_in[3];
    float* out = (float*)d_out;

    cudaFuncSetAttribute(k2_attn_mma, cudaFuncAttributeMaxDynamicSharedMemorySize, SMEM_BYTES);

    k1_proj<<<256, 128>>>(x, W, a);
    k1b_transpose<<<NN / 64, 256>>>();
    k2_attn_mma<<<dim3(NN / ITILE, NSPLIT), 128, SMEM_BYTES>>>(adj);
    k3_reduce<<<(NN * OUTD / 4) / 128, 128>>>(out);
}

// round 10
// speedup vs baseline: 1.2292x; 1.2292x over previous
#include <cuda_runtime.h>
#include <cuda_bf16.h>
#include <cstdint>

#define NN   8192
#define IND  128
#define OUTD 64
#define NSPLIT 6               // uneven j-splits: tiles 43,43,43,43,42,42
#define TOTTILES 256           // 8192 / 32
#define JT 32                  // K tile
#define ITILE 128              // M rows per block
#define ASTR 40                // A row stride (bf16 elems)
#define BSTR 40                // B row stride

// smem elem offsets (bf16), double buffered
#define OFF_AH(b) ((b) * 5120)
#define OFF_AL(b) (10240 + (b) * 5120)
#define OFF_BH(b) (20480 + (b) * 2560)
#define OFF_BL(b) (25600 + (b) * 2560)
#define SMEM_ELEMS 30720
#define SMEM_BYTES (SMEM_ELEMS * 2)

// static device scratch (no allocations allowed)
__device__ float g_Wh[(size_t)NN * OUTD];
__device__ float g_s1[NN];
__device__ float g_s2[NN];
__device__ __nv_bfloat16 g_WhT_hi[(size_t)OUTD * NN];  // [d][j]
__device__ __nv_bfloat16 g_WhT_lo[(size_t)OUTD * NN];
__device__ float g_part[(size_t)NSPLIT * NN * OUTD];
__device__ float g_lp[(size_t)NSPLIT * NN];

__device__ __forceinline__ uint32_t smem_u32(const void* p) {
    return (uint32_t)__cvta_generic_to_shared(p);
}
__device__ __forceinline__ void ldsm_x4(uint32_t& r0, uint32_t& r1, uint32_t& r2, uint32_t& r3, uint32_t a) {
    asm volatile("ldmatrix.sync.aligned.m8n8.x4.shared.b16 {%0,%1,%2,%3}, [%4];"
                 : "=r"(r0), "=r"(r1), "=r"(r2), "=r"(r3) : "r"(a));
}
__device__ __forceinline__ void ldsm_x2(uint32_t& r0, uint32_t& r1, uint32_t a) {
    asm volatile("ldmatrix.sync.aligned.m8n8.x2.shared.b16 {%0,%1}, [%2];"
                 : "=r"(r0), "=r"(r1) : "r"(a));
}
__device__ __forceinline__ void mma_bf16(float* c, const uint32_t* A, uint32_t b0, uint32_t b1) {
    asm volatile(
        "mma.sync.aligned.m16n8k16.row.col.f32.bf16.bf16.f32 "
        "{%0,%1,%2,%3}, {%4,%5,%6,%7}, {%8,%9}, {%0,%1,%2,%3};"
        : "+f"(c[0]), "+f"(c[1]), "+f"(c[2]), "+f"(c[3])
        : "r"(A[0]), "r"(A[1]), "r"(A[2]), "r"(A[3]), "r"(b0), "r"(b1));
}

// ---------------------------------------------------------------------------
// K1: Wh = x@W (fp32, coalesced); s1/s2 = Wh@a halves
// ---------------------------------------------------------------------------
__global__ __launch_bounds__(128) void k1_proj(const float* __restrict__ x,
                                               const float* __restrict__ W,
                                               const float* __restrict__ a) {
    __shared__ float W_sm[IND][OUTD];
    __shared__ float x_sm[32][33];

    const int t  = threadIdx.x;
    const int i0 = blockIdx.x * 32;
    const int dl = t & 15;
    const int rl = t >> 4;

    {
        const float4* src = (const float4*)W;
        float4* dst = (float4*)&W_sm[0][0];
#pragma unroll
        for (int q = 0; q < 16; ++q) dst[t + 128 * q] = src[t + 128 * q];
    }

    float acc[4][4];
#pragma unroll
    for (int rr = 0; rr < 4; ++rr)
#pragma unroll
        for (int dd = 0; dd < 4; ++dd) acc[rr][dd] = 0.f;

    for (int k0 = 0; k0 < IND; k0 += 32) {
        __syncthreads();
#pragma unroll
        for (int q = 0; q < 8; ++q) {
            int idx = t + 128 * q;
            int r = idx >> 5, kk = idx & 31;
            x_sm[r][kk] = x[(size_t)(i0 + r) * IND + k0 + kk];
        }
        __syncthreads();
#pragma unroll
        for (int kk = 0; kk < 32; ++kk) {
            float4 w = *(const float4*)&W_sm[k0 + kk][dl * 4];
#pragma unroll
            for (int rr = 0; rr < 4; ++rr) {
                float xv = x_sm[rl * 4 + rr][kk];
                acc[rr][0] += xv * w.x;
                acc[rr][1] += xv * w.y;
                acc[rr][2] += xv * w.z;
                acc[rr][3] += xv * w.w;
            }
        }
    }

    const float* a1 = a;
    const float* a2 = a + OUTD;
#pragma unroll
    for (int rr = 0; rr < 4; ++rr) {
        int row = i0 + rl * 4 + rr;
        *(float4*)&g_Wh[(size_t)row * OUTD + dl * 4] =
            make_float4(acc[rr][0], acc[rr][1], acc[rr][2], acc[rr][3]);
        float4 av1 = *(const float4*)&a1[dl * 4];
        float4 av2 = *(const float4*)&a2[dl * 4];
        float v1 = acc[rr][0] * av1.x + acc[rr][1] * av1.y + acc[rr][2] * av1.z + acc[rr][3] * av1.w;
        float v2 = acc[rr][0] * av2.x + acc[rr][1] * av2.y + acc[rr][2] * av2.z + acc[rr][3] * av2.w;
#pragma unroll
        for (int o = 8; o >= 1; o >>= 1) {
            v1 += __shfl_xor_sync(0xffffffffu, v1, o, 16);
            v2 += __shfl_xor_sync(0xffffffffu, v2, o, 16);
        }
        if (dl == 0) { g_s1[row] = v1; g_s2[row] = v2; }
    }
}

// ---------------------------------------------------------------------------
// K1b: transpose Wh -> WhT hi/lo bf16, coalesced both ways via smem tile
// ---------------------------------------------------------------------------
__global__ __launch_bounds__(256) void k1b_transpose() {
    __shared__ float ts[64][68];
    const int t  = threadIdx.x;
    const int j0 = blockIdx.x * 64;

#pragma unroll
    for (int q = 0; q < 4; ++q) {
        int idx = t + 256 * q;
        int r = idx >> 4, c4 = (idx & 15) * 4;
        *(float4*)&ts[r][c4] = *(const float4*)&g_Wh[(size_t)(j0 + r) * OUTD + c4];
    }
    __syncthreads();

    const int d  = t >> 2;
    const int jq = (t & 3) * 16;
    uint32_t hi[8], lo[8];
#pragma unroll
    for (int u = 0; u < 8; ++u) {
        float v0 = ts[jq + 2 * u][d];
        float v1 = ts[jq + 2 * u + 1][d];
        __nv_bfloat162 h = __float22bfloat162_rn(make_float2(v0, v1));
        uint32_t uh = *(uint32_t*)&h;
        hi[u] = uh;
        float r0 = v0 - __uint_as_float(uh << 16);
        float r1 = v1 - __uint_as_float(uh & 0xffff0000u);
        __nv_bfloat162 l = __float22bfloat162_rn(make_float2(r0, r1));
        lo[u] = *(uint32_t*)&l;
    }
    __nv_bfloat16* dh = g_WhT_hi + (size_t)d * NN + j0 + jq;
    __nv_bfloat16* dl = g_WhT_lo + (size_t)d * NN + j0 + jq;
    *(uint4*)dh       = make_uint4(hi[0], hi[1], hi[2], hi[3]);
    *(uint4*)(dh + 8) = make_uint4(hi[4], hi[5], hi[6], hi[7]);
    *(uint4*)dl       = make_uint4(lo[0], lo[1], lo[2], lo[3]);
    *(uint4*)(dl + 8) = make_uint4(lo[4], lo[5], lo[6], lo[7]);
}

// ---------------------------------------------------------------------------
// K2: software-pipelined (R8 layout), uneven j-splits for a single wave.
// grid = (64, 6) = 384 blocks @ 3 blocks/SM -> one wave on 148 SMs.
// ---------------------------------------------------------------------------
__global__ __launch_bounds__(128, 3) void k2_attn_mma(const int* __restrict__ adj) {
    extern __shared__ __nv_bfloat16 sm[];

    const int t     = threadIdx.x;
    const int wid   = t >> 5;
    const int lid   = t & 31;
    const int i0    = blockIdx.x * ITILE;
    const int split = blockIdx.y;

    // uneven split: base 42, first 4 splits get +1
    const int base  = TOTTILES / NSPLIT;          // 42
    const int rem   = TOTTILES % NSPLIT;          // 4
    const int start = split * base + (split < rem ? split : rem);
    const int cnt   = base + (split < rem ? 1 : 0);
    const int js    = start * JT;

    const float s1v = g_s1[i0 + t];
    const int* adjrow = adj + (size_t)(i0 + t) * NN + js;
    const int bn = t >> 1, bk = (t & 1) * 16;
    const __nv_bfloat16* bhp = g_WhT_hi + (size_t)bn * NN + js + bk;
    const __nv_bfloat16* blp = g_WhT_lo + (size_t)bn * NN + js + bk;

    float lacc = 0.f;
    float c[2][8][4];
#pragma unroll
    for (int mt = 0; mt < 2; ++mt)
#pragma unroll
        for (int nt = 0; nt < 8; ++nt)
#pragma unroll
            for (int q = 0; q < 4; ++q) c[mt][nt][q] = 0.f;

    auto build = [&](int tl, int b, const int4* pa) {
        const int j0 = tl * JT;
        {
            const __nv_bfloat16* sh = bhp + j0;
            const __nv_bfloat16* sl = blp + j0;
            __nv_bfloat16* Bh = sm + OFF_BH(b) + bn * BSTR + bk;
            __nv_bfloat16* Bl = sm + OFF_BL(b) + bn * BSTR + bk;
            *(uint4*)Bh       = *(const uint4*)sh;
            *(uint4*)(Bh + 8) = *(const uint4*)(sh + 8);
            *(uint4*)Bl       = *(const uint4*)sl;
            *(uint4*)(Bl + 8) = *(const uint4*)(sl + 8);
        }
        const float4* s4p = (const float4*)(g_s2 + js + j0);
        __nv_bfloat16* Ah = sm + OFF_AH(b) + t * ASTR;
        __nv_bfloat16* Al = sm + OFF_AL(b) + t * ASTR;
#pragma unroll
        for (int k = 0; k < 4; ++k) {
            int4   aA = pa[2 * k], aB = pa[2 * k + 1];
            float4 sA = s4p[2 * k], sB = s4p[2 * k + 1];
            float p0, p1, p2, p3, p4, p5, p6, p7, e;
            e = s1v + sA.x; e = fmaxf(e, 0.2f * e); p0 = aA.x ? __expf(e) : 0.f;
            e = s1v + sA.y; e = fmaxf(e, 0.2f * e); p1 = aA.y ? __expf(e) : 0.f;
            e = s1v + sA.z; e = fmaxf(e, 0.2f * e); p2 = aA.z ? __expf(e) : 0.f;
            e = s1v + sA.w; e = fmaxf(e, 0.2f * e); p3 = aA.w ? __expf(e) : 0.f;
            e = s1v + sB.x; e = fmaxf(e, 0.2f * e); p4 = aB.x ? __expf(e) : 0.f;
            e = s1v + sB.y; e = fmaxf(e, 0.2f * e); p5 = aB.y ? __expf(e) : 0.f;
            e = s1v + sB.z; e = fmaxf(e, 0.2f * e); p6 = aB.z ? __expf(e) : 0.f;
            e = s1v + sB.w; e = fmaxf(e, 0.2f * e); p7 = aB.w ? __expf(e) : 0.f;
            lacc += ((p0 + p1) + (p2 + p3)) + ((p4 + p5) + (p6 + p7));

            __nv_bfloat162 h01 = __float22bfloat162_rn(make_float2(p0, p1));
            __nv_bfloat162 h23 = __float22bfloat162_rn(make_float2(p2, p3));
            __nv_bfloat162 h45 = __float22bfloat162_rn(make_float2(p4, p5));
            __nv_bfloat162 h67 = __float22bfloat162_rn(make_float2(p6, p7));
            uint32_t u01 = *(uint32_t*)&h01, u23 = *(uint32_t*)&h23;
            uint32_t u45 = *(uint32_t*)&h45, u67 = *(uint32_t*)&h67;
            *(uint4*)(Ah + k * 8) = make_uint4(u01, u23, u45, u67);

            float l0 = p0 - __uint_as_float(u01 << 16);
            float l1 = p1 - __uint_as_float(u01 & 0xffff0000u);
            float l2 = p2 - __uint_as_float(u23 << 16);
            float l3 = p3 - __uint_as_float(u23 & 0xffff0000u);
            float l4 = p4 - __uint_as_float(u45 << 16);
            float l5 = p5 - __uint_as_float(u45 & 0xffff0000u);
            float l6 = p6 - __uint_as_float(u67 << 16);
            float l7 = p7 - __uint_as_float(u67 & 0xffff0000u);
            __nv_bfloat162 q01 = __float22bfloat162_rn(make_float2(l0, l1));
            __nv_bfloat162 q23 = __float22bfloat162_rn(make_float2(l2, l3));
            __nv_bfloat162 q45 = __float22bfloat162_rn(make_float2(l4, l5));
            __nv_bfloat162 q67 = __float22bfloat162_rn(make_float2(l6, l7));
            *(uint4*)(Al + k * 8) = make_uint4(*(uint32_t*)&q01, *(uint32_t*)&q23,
                                               *(uint32_t*)&q45, *(uint32_t*)&q67);
        }
    };

    // prologue: build tile 0 into buffer 0
    {
        int4 pa[8];
#pragma unroll
        for (int q = 0; q < 8; ++q) pa[q] = ((const int4*)adjrow)[q];
        build(0, 0, pa);
    }
    __syncthreads();

    const uint32_t ROWB = ASTR * 2;   // 80 B
    const int bl = lid & 15;

    for (int tile = 0; tile < cnt; ++tile) {
        const int cur = tile & 1, nb = cur ^ 1;

        int4 pa[8];
        if (tile + 1 < cnt) {
            const int4* src = (const int4*)(adjrow + (tile + 1) * JT);
#pragma unroll
            for (int q = 0; q < 8; ++q) pa[q] = src[q];
        }

        // ---- MMA on buffer cur
        const uint32_t a0 = smem_u32(sm + OFF_AH(cur) + (wid * 32 + (lid & 15)) * ASTR + (lid >> 4) * 8);
        const uint32_t a1 = smem_u32(sm + OFF_AL(cur) + (wid * 32 + (lid & 15)) * ASTR + (lid >> 4) * 8);
        const uint32_t b0a = smem_u32(sm + OFF_BH(cur) + (bl & 7) * BSTR + (bl >> 3) * 8);
        const uint32_t b1a = smem_u32(sm + OFF_BL(cur) + (bl & 7) * BSTR + (bl >> 3) * 8);
#pragma unroll
        for (int kt = 0; kt < 2; ++kt) {
            uint32_t Ah[2][4], Al[2][4];
#pragma unroll
            for (int mt = 0; mt < 2; ++mt) {
                ldsm_x4(Ah[mt][0], Ah[mt][1], Ah[mt][2], Ah[mt][3],
                        a0 + (uint32_t)(mt * 16) * ROWB + kt * 32);
                ldsm_x4(Al[mt][0], Al[mt][1], Al[mt][2], Al[mt][3],
                        a1 + (uint32_t)(mt * 16) * ROWB + kt * 32);
            }
#pragma unroll
            for (int nt = 0; nt < 8; ++nt) {
                uint32_t bh0, bh1, blo0, blo1;
                ldsm_x2(bh0, bh1, b0a + (uint32_t)(nt * 8) * ROWB + kt * 32);
                ldsm_x2(blo0, blo1, b1a + (uint32_t)(nt * 8) * ROWB + kt * 32);
#pragma unroll
                for (int mt = 0; mt < 2; ++mt) {
                    mma_bf16(c[mt][nt], Ah[mt], bh0, bh1);
                    mma_bf16(c[mt][nt], Ah[mt], blo0, blo1);
                    mma_bf16(c[mt][nt], Al[mt], bh0, bh1);
                }
            }
        }

        // ---- build tile+1 into buffer nb
        if (tile + 1 < cnt) build(tile + 1, nb, pa);
        __syncthreads();
    }

    g_lp[(size_t)split * NN + i0 + t] = lacc;

    // ---- epilogue: raw partials
    const int rbase = i0 + wid * 32 + (lid >> 2);
    const int cbase = 2 * (lid & 3);
#pragma unroll
    for (int mt = 0; mt < 2; ++mt) {
#pragma unroll
        for (int nt = 0; nt < 8; ++nt) {
            const int col = nt * 8 + cbase;
            float* d0 = &g_part[((size_t)split * NN + rbase + mt * 16) * OUTD + col];
            float* d1 = &g_part[((size_t)split * NN + rbase + mt * 16 + 8) * OUTD + col];
            *(float2*)d0 = make_float2(c[mt][nt][0], c[mt][nt][1]);
            *(float2*)d1 = make_float2(c[mt][nt][2], c[mt][nt][3]);
        }
    }
}

// ---------------------------------------------------------------------------
// K3: reduce NSPLIT partials, normalize, ELU.
// ---------------------------------------------------------------------------
__global__ __launch_bounds__(128) void k3_reduce(float* __restrict__ out) {
    const int q   = blockIdx.x * 128 + threadIdx.x;
    const int row = q >> 4;
    const int c4  = (q & 15) * 4;

    float l = 0.f;
#pragma unroll
    for (int s = 0; s < NSPLIT; ++s) l += g_lp[(size_t)s * NN + row];
    const float inv = 1.0f / l;

    float4 acc = make_float4(0.f, 0.f, 0.f, 0.f);
#pragma unroll
    for (int s = 0; s < NSPLIT; ++s) {
        float4 v = *(const float4*)&g_part[((size_t)s * NN + row) * OUTD + c4];
        acc.x += v.x; acc.y += v.y; acc.z += v.z; acc.w += v.w;
    }
    acc.x *= inv; acc.y *= inv; acc.z *= inv; acc.w *= inv;
    acc.x = acc.x > 0.f ? acc.x : expm1f(acc.x);
    acc.y = acc.y > 0.f ? acc.y : expm1f(acc.y);
    acc.z = acc.z > 0.f ? acc.z : expm1f(acc.z);
    acc.w = acc.w > 0.f ? acc.w : expm1f(acc.w);
    *(float4*)&out[(size_t)row * OUTD + c4] = acc;
}

extern "C" void kernel_launch(void* const* d_in, const int* in_sizes, int n_in,
                              void* d_out, int out_size) {
    const float* x   = (const float*)d_in[0];
    const int*   adj = (const int*)d_in[1];
    const float* W   = (const float*)d_in[2];
    const float* a   = (const float*)d_in[3];
    float* out = (float*)d_out;

    cudaFuncSetAttribute(k2_attn_mma, cudaFuncAttributeMaxDynamicSharedMemorySize, SMEM_BYTES);

    k1_proj<<<256, 128>>>(x, W, a);
    k1b_transpose<<<NN / 64, 256>>>();
    k2_attn_mma<<<dim3(NN / ITILE, NSPLIT), 128, SMEM_BYTES>>>(adj);
    k3_reduce<<<(NN * OUTD / 4) / 128, 128>>>(out);
}

// round 11
// speedup vs baseline: 1.3616x; 1.1077x over previous
#include <cuda_runtime.h>
#include <cuda_bf16.h>
#include <cstdint>

#define NN   8192
#define IND  128
#define OUTD 64
#define NSPLIT 6               // uneven j-splits: tiles 43,43,43,43,42,42
#define TOTTILES 256           // 8192 / 32
#define JT 32                  // K tile
#define ITILE 128              // M rows per block
#define ASTR 40                // A row stride (bf16 elems)
#define BSTR 40                // B row stride

// smem elem offsets (bf16), double buffered
#define OFF_AH(b) ((b) * 5120)
#define OFF_AL(b) (10240 + (b) * 5120)
#define OFF_BH(b) (20480 + (b) * 2560)
#define OFF_BL(b) (25600 + (b) * 2560)
#define SMEM_ELEMS 30720
#define SMEM_BYTES (SMEM_ELEMS * 2)

// static device scratch (no allocations allowed)
__device__ float g_Wh[(size_t)NN * OUTD];
__device__ float g_s1[NN];
__device__ float g_s2[NN];
__device__ __nv_bfloat16 g_WhT_hi[(size_t)OUTD * NN];  // [d][j]
__device__ __nv_bfloat16 g_WhT_lo[(size_t)OUTD * NN];
__device__ float g_part[(size_t)NSPLIT * NN * OUTD];
__device__ float g_lp[(size_t)NSPLIT * NN];

__device__ __forceinline__ uint32_t smem_u32(const void* p) {
    return (uint32_t)__cvta_generic_to_shared(p);
}
__device__ __forceinline__ void ldsm_x4(uint32_t& r0, uint32_t& r1, uint32_t& r2, uint32_t& r3, uint32_t a) {
    asm volatile("ldmatrix.sync.aligned.m8n8.x4.shared.b16 {%0,%1,%2,%3}, [%4];"
                 : "=r"(r0), "=r"(r1), "=r"(r2), "=r"(r3) : "r"(a));
}
__device__ __forceinline__ void ldsm_x2(uint32_t& r0, uint32_t& r1, uint32_t a) {
    asm volatile("ldmatrix.sync.aligned.m8n8.x2.shared.b16 {%0,%1}, [%2];"
                 : "=r"(r0), "=r"(r1) : "r"(a));
}
__device__ __forceinline__ void mma_bf16(float* c, const uint32_t* A, uint32_t b0, uint32_t b1) {
    asm volatile(
        "mma.sync.aligned.m16n8k16.row.col.f32.bf16.bf16.f32 "
        "{%0,%1,%2,%3}, {%4,%5,%6,%7}, {%8,%9}, {%0,%1,%2,%3};"
        : "+f"(c[0]), "+f"(c[1]), "+f"(c[2]), "+f"(c[3])
        : "r"(A[0]), "r"(A[1]), "r"(A[2]), "r"(A[3]), "r"(b0), "r"(b1));
}

// ---------------------------------------------------------------------------
// K1: Wh = x@W (fp32, coalesced); s1/s2 = Wh@a halves
// ---------------------------------------------------------------------------
__global__ __launch_bounds__(128) void k1_proj(const float* __restrict__ x,
                                               const float* __restrict__ W,
                                               const float* __restrict__ a) {
    __shared__ float W_sm[IND][OUTD];
    __shared__ float x_sm[32][33];

    const int t  = threadIdx.x;
    const int i0 = blockIdx.x * 32;
    const int dl = t & 15;
    const int rl = t >> 4;

    {
        const float4* src = (const float4*)W;
        float4* dst = (float4*)&W_sm[0][0];
#pragma unroll
        for (int q = 0; q < 16; ++q) dst[t + 128 * q] = src[t + 128 * q];
    }

    float acc[4][4];
#pragma unroll
    for (int rr = 0; rr < 4; ++rr)
#pragma unroll
        for (int dd = 0; dd < 4; ++dd) acc[rr][dd] = 0.f;

    for (int k0 = 0; k0 < IND; k0 += 32) {
        __syncthreads();
#pragma unroll
        for (int q = 0; q < 8; ++q) {
            int idx = t + 128 * q;
            int r = idx >> 5, kk = idx & 31;
            x_sm[r][kk] = x[(size_t)(i0 + r) * IND + k0 + kk];
        }
        __syncthreads();
#pragma unroll
        for (int kk = 0; kk < 32; ++kk) {
            float4 w = *(const float4*)&W_sm[k0 + kk][dl * 4];
#pragma unroll
            for (int rr = 0; rr < 4; ++rr) {
                float xv = x_sm[rl * 4 + rr][kk];
                acc[rr][0] += xv * w.x;
                acc[rr][1] += xv * w.y;
                acc[rr][2] += xv * w.z;
                acc[rr][3] += xv * w.w;
            }
        }
    }

    const float* a1 = a;
    const float* a2 = a + OUTD;
#pragma unroll
    for (int rr = 0; rr < 4; ++rr) {
        int row = i0 + rl * 4 + rr;
        *(float4*)&g_Wh[(size_t)row * OUTD + dl * 4] =
            make_float4(acc[rr][0], acc[rr][1], acc[rr][2], acc[rr][3]);
        float4 av1 = *(const float4*)&a1[dl * 4];
        float4 av2 = *(const float4*)&a2[dl * 4];
        float v1 = acc[rr][0] * av1.x + acc[rr][1] * av1.y + acc[rr][2] * av1.z + acc[rr][3] * av1.w;
        float v2 = acc[rr][0] * av2.x + acc[rr][1] * av2.y + acc[rr][2] * av2.z + acc[rr][3] * av2.w;
#pragma unroll
        for (int o = 8; o >= 1; o >>= 1) {
            v1 += __shfl_xor_sync(0xffffffffu, v1, o, 16);
            v2 += __shfl_xor_sync(0xffffffffu, v2, o, 16);
        }
        if (dl == 0) { g_s1[row] = v1; g_s2[row] = v2; }
    }
}

// ---------------------------------------------------------------------------
// K1b: transpose Wh -> WhT hi/lo bf16
// ---------------------------------------------------------------------------
__global__ __launch_bounds__(256) void k1b_transpose() {
    __shared__ float ts[64][68];
    const int t  = threadIdx.x;
    const int j0 = blockIdx.x * 64;

#pragma unroll
    for (int q = 0; q < 4; ++q) {
        int idx = t + 256 * q;
        int r = idx >> 4, c4 = (idx & 15) * 4;
        *(float4*)&ts[r][c4] = *(const float4*)&g_Wh[(size_t)(j0 + r) * OUTD + c4];
    }
    __syncthreads();

    const int d  = t >> 2;
    const int jq = (t & 3) * 16;
    uint32_t hi[8], lo[8];
#pragma unroll
    for (int u = 0; u < 8; ++u) {
        float v0 = ts[jq + 2 * u][d];
        float v1 = ts[jq + 2 * u + 1][d];
        __nv_bfloat162 h = __float22bfloat162_rn(make_float2(v0, v1));
        uint32_t uh = *(uint32_t*)&h;
        hi[u] = uh;
        float r0 = v0 - __uint_as_float(uh << 16);
        float r1 = v1 - __uint_as_float(uh & 0xffff0000u);
        __nv_bfloat162 l = __float22bfloat162_rn(make_float2(r0, r1));
        lo[u] = *(uint32_t*)&l;
    }
    __nv_bfloat16* dh = g_WhT_hi + (size_t)d * NN + j0 + jq;
    __nv_bfloat16* dl = g_WhT_lo + (size_t)d * NN + j0 + jq;
    *(uint4*)dh       = make_uint4(hi[0], hi[1], hi[2], hi[3]);
    *(uint4*)(dh + 8) = make_uint4(hi[4], hi[5], hi[6], hi[7]);
    *(uint4*)dl       = make_uint4(lo[0], lo[1], lo[2], lo[3]);
    *(uint4*)(dl + 8) = make_uint4(lo[4], lo[5], lo[6], lo[7]);
}

// ---------------------------------------------------------------------------
// K2: software-pipelined, 256 threads / 8 warps (each warp owns m16),
// uneven j-splits for a single wave. grid = (64, 6) = 384 blocks @ 3/SM.
// ---------------------------------------------------------------------------
__global__ __launch_bounds__(256, 3) void k2_attn_mma(const int* __restrict__ adj) {
    extern __shared__ __nv_bfloat16 sm[];

    const int t     = threadIdx.x;
    const int wid   = t >> 5;
    const int lid   = t & 31;
    const int i0    = blockIdx.x * ITILE;
    const int split = blockIdx.y;

    // uneven split: base 42, first 4 splits get +1
    const int base  = TOTTILES / NSPLIT;
    const int rem   = TOTTILES % NSPLIT;
    const int start = split * base + (split < rem ? split : rem);
    const int cnt   = base + (split < rem ? 1 : 0);
    const int js    = start * JT;

    // A-phase role: row = t>>1, 16-j half = (t&1)*16
    const int arow  = t >> 1;
    const int ahalf = (t & 1) * 16;
    const float s1v = g_s1[i0 + arow];
    const int* adjrow = adj + (size_t)(i0 + arow) * NN + js + ahalf;

    // B-phase role: row = t>>2, quarter = (t&3)*8
    const int bn = t >> 2, bk = (t & 3) * 8;
    const __nv_bfloat16* bhp = g_WhT_hi + (size_t)bn * NN + js + bk;
    const __nv_bfloat16* blp = g_WhT_lo + (size_t)bn * NN + js + bk;

    float lacc = 0.f;
    float c[8][4];
#pragma unroll
    for (int nt = 0; nt < 8; ++nt)
#pragma unroll
        for (int q = 0; q < 4; ++q) c[nt][q] = 0.f;

    auto build = [&](int tl, int b, const int4* pa) {
        const int j0 = tl * JT;
        // B tile: one uint4 hi + lo per thread
        {
            *(uint4*)(sm + OFF_BH(b) + bn * BSTR + bk) = *(const uint4*)(bhp + j0);
            *(uint4*)(sm + OFF_BL(b) + bn * BSTR + bk) = *(const uint4*)(blp + j0);
        }
        // A tile: 16 p values (2 k-iters of 8)
        const float4* s4p = (const float4*)(g_s2 + js + j0 + ahalf);
        __nv_bfloat16* Ah = sm + OFF_AH(b) + arow * ASTR + ahalf;
        __nv_bfloat16* Al = sm + OFF_AL(b) + arow * ASTR + ahalf;
#pragma unroll
        for (int k = 0; k < 2; ++k) {
            int4   aA = pa[2 * k], aB = pa[2 * k + 1];
            float4 sA = s4p[2 * k], sB = s4p[2 * k + 1];
            float p0, p1, p2, p3, p4, p5, p6, p7, e;
            e = s1v + sA.x; e = fmaxf(e, 0.2f * e); p0 = aA.x ? __expf(e) : 0.f;
            e = s1v + sA.y; e = fmaxf(e, 0.2f * e); p1 = aA.y ? __expf(e) : 0.f;
            e = s1v + sA.z; e = fmaxf(e, 0.2f * e); p2 = aA.z ? __expf(e) : 0.f;
            e = s1v + sA.w; e = fmaxf(e, 0.2f * e); p3 = aA.w ? __expf(e) : 0.f;
            e = s1v + sB.x; e = fmaxf(e, 0.2f * e); p4 = aB.x ? __expf(e) : 0.f;
            e = s1v + sB.y; e = fmaxf(e, 0.2f * e); p5 = aB.y ? __expf(e) : 0.f;
            e = s1v + sB.z; e = fmaxf(e, 0.2f * e); p6 = aB.z ? __expf(e) : 0.f;
            e = s1v + sB.w; e = fmaxf(e, 0.2f * e); p7 = aB.w ? __expf(e) : 0.f;
            lacc += ((p0 + p1) + (p2 + p3)) + ((p4 + p5) + (p6 + p7));

            __nv_bfloat162 h01 = __float22bfloat162_rn(make_float2(p0, p1));
            __nv_bfloat162 h23 = __float22bfloat162_rn(make_float2(p2, p3));
            __nv_bfloat162 h45 = __float22bfloat162_rn(make_float2(p4, p5));
            __nv_bfloat162 h67 = __float22bfloat162_rn(make_float2(p6, p7));
            uint32_t u01 = *(uint32_t*)&h01, u23 = *(uint32_t*)&h23;
            uint32_t u45 = *(uint32_t*)&h45, u67 = *(uint32_t*)&h67;
            *(uint4*)(Ah + k * 8) = make_uint4(u01, u23, u45, u67);

            float l0 = p0 - __uint_as_float(u01 << 16);
            float l1 = p1 - __uint_as_float(u01 & 0xffff0000u);
            float l2 = p2 - __uint_as_float(u23 << 16);
            float l3 = p3 - __uint_as_float(u23 & 0xffff0000u);
            float l4 = p4 - __uint_as_float(u45 << 16);
            float l5 = p5 - __uint_as_float(u45 & 0xffff0000u);
            float l6 = p6 - __uint_as_float(u67 << 16);
            float l7 = p7 - __uint_as_float(u67 & 0xffff0000u);
            __nv_bfloat162 q01 = __float22bfloat162_rn(make_float2(l0, l1));
            __nv_bfloat162 q23 = __float22bfloat162_rn(make_float2(l2, l3));
            __nv_bfloat162 q45 = __float22bfloat162_rn(make_float2(l4, l5));
            __nv_bfloat162 q67 = __float22bfloat162_rn(make_float2(l6, l7));
            *(uint4*)(Al + k * 8) = make_uint4(*(uint32_t*)&q01, *(uint32_t*)&q23,
                                               *(uint32_t*)&q45, *(uint32_t*)&q67);
        }
    };

    // prologue: build tile 0 into buffer 0
    {
        int4 pa[4];
#pragma unroll
        for (int q = 0; q < 4; ++q) pa[q] = ((const int4*)adjrow)[q];
        build(0, 0, pa);
    }
    __syncthreads();

    const uint32_t ROWB = ASTR * 2;   // 80 B
    const int bl = lid & 15;

    for (int tile = 0; tile < cnt; ++tile) {
        const int cur = tile & 1, nb = cur ^ 1;

        int4 pa[4];
        if (tile + 1 < cnt) {
            const int4* src = (const int4*)(adjrow + (tile + 1) * JT);
#pragma unroll
            for (int q = 0; q < 4; ++q) pa[q] = src[q];
        }

        // ---- MMA on buffer cur: warp = m16 x n64 x k32, 3 terms
        const uint32_t a0 = smem_u32(sm + OFF_AH(cur) + (wid * 16 + (lid & 15)) * ASTR + (lid >> 4) * 8);
        const uint32_t a1 = smem_u32(sm + OFF_AL(cur) + (wid * 16 + (lid & 15)) * ASTR + (lid >> 4) * 8);
        const uint32_t b0a = smem_u32(sm + OFF_BH(cur) + (bl & 7) * BSTR + (bl >> 3) * 8);
        const uint32_t b1a = smem_u32(sm + OFF_BL(cur) + (bl & 7) * BSTR + (bl >> 3) * 8);
#pragma unroll
        for (int kt = 0; kt < 2; ++kt) {
            uint32_t Ah[4], Al[4];
            ldsm_x4(Ah[0], Ah[1], Ah[2], Ah[3], a0 + kt * 32);
            ldsm_x4(Al[0], Al[1], Al[2], Al[3], a1 + kt * 32);
#pragma unroll
            for (int nt = 0; nt < 8; ++nt) {
                uint32_t bh0, bh1, blo0, blo1;
                ldsm_x2(bh0, bh1, b0a + (uint32_t)(nt * 8) * ROWB + kt * 32);
                ldsm_x2(blo0, blo1, b1a + (uint32_t)(nt * 8) * ROWB + kt * 32);
                mma_bf16(c[nt], Ah, bh0, bh1);
                mma_bf16(c[nt], Ah, blo0, blo1);
                mma_bf16(c[nt], Al, bh0, bh1);
            }
        }

        // ---- build tile+1 into buffer nb
        if (tile + 1 < cnt) build(tile + 1, nb, pa);
        __syncthreads();
    }

    // l: the two half-row threads are adjacent lanes
    lacc += __shfl_xor_sync(0xffffffffu, lacc, 1);
    if ((t & 1) == 0) g_lp[(size_t)split * NN + i0 + arow] = lacc;

    // ---- epilogue: raw partials
    const int rbase = i0 + wid * 16 + (lid >> 2);
    const int cbase = 2 * (lid & 3);
#pragma unroll
    for (int nt = 0; nt < 8; ++nt) {
        const int col = nt * 8 + cbase;
        float* d0 = &g_part[((size_t)split * NN + rbase) * OUTD + col];
        float* d1 = &g_part[((size_t)split * NN + rbase + 8) * OUTD + col];
        *(float2*)d0 = make_float2(c[nt][0], c[nt][1]);
        *(float2*)d1 = make_float2(c[nt][2], c[nt][3]);
    }
}

// ---------------------------------------------------------------------------
// K3: reduce NSPLIT partials, normalize, ELU.
// ---------------------------------------------------------------------------
__global__ __launch_bounds__(128) void k3_reduce(float* __restrict__ out) {
    const int q   = blockIdx.x * 128 + threadIdx.x;
    const int row = q >> 4;
    const int c4  = (q & 15) * 4;

    float l = 0.f;
#pragma unroll
    for (int s = 0; s < NSPLIT; ++s) l += g_lp[(size_t)s * NN + row];
    const float inv = 1.0f / l;

    float4 acc = make_float4(0.f, 0.f, 0.f, 0.f);
#pragma unroll
    for (int s = 0; s < NSPLIT; ++s) {
        float4 v = *(const float4*)&g_part[((size_t)s * NN + row) * OUTD + c4];
        acc.x += v.x; acc.y += v.y; acc.z += v.z; acc.w += v.w;
    }
    acc.x *= inv; acc.y *= inv; acc.z *= inv; acc.w *= inv;
    acc.x = acc.x > 0.f ? acc.x : expm1f(acc.x);
    acc.y = acc.y > 0.f ? acc.y : expm1f(acc.y);
    acc.z = acc.z > 0.f ? acc.z : expm1f(acc.z);
    acc.w = acc.w > 0.f ? acc.w : expm1f(acc.w);
    *(float4*)&out[(size_t)row * OUTD + c4] = acc;
}

extern "C" void kernel_launch(void* const* d_in, const int* in_sizes, int n_in,
                              void* d_out, int out_size) {
    const float* x   = (const float*)d_in[0];
    const int*   adj = (const int*)d_in[1];
    const float* W   = (const float*)d_in[2];
    const float* a   = (const float*)d_in[3];
    float* out = (float*)d_out;

    cudaFuncSetAttribute(k2_attn_mma, cudaFuncAttributeMaxDynamicSharedMemorySize, SMEM_BYTES);

    k1_proj<<<256, 128>>>(x, W, a);
    k1b_transpose<<<NN / 64, 256>>>();
    k2_attn_mma<<<dim3(NN / ITILE, NSPLIT), 256, SMEM_BYTES>>>(adj);
    k3_reduce<<<(NN * OUTD / 4) / 128, 128>>>(out);
}

// round 12
// speedup vs baseline: 1.5951x; 1.1715x over previous
#include <cuda_runtime.h>
#include <cuda_fp16.h>
#include <cstdint>

#define NN   8192
#define IND  128
#define OUTD 64
#define NSPLIT 6               // uneven j-splits: tiles 43,43,43,43,42,42
#define TOTTILES 256           // 8192 / 32
#define JT 32                  // K tile
#define ITILE 128              // M rows per block
#define ASTR 40                // A row stride (fp16 elems)
#define BSTR 40                // B row stride

// smem elem offsets (fp16), double buffered. A = p (hi only), B = W hi/lo.
#define OFF_A(b)  ((b) * 5120)
#define OFF_BH(b) (10240 + (b) * 2560)
#define OFF_BL(b) (15360 + (b) * 2560)
#define SMEM_ELEMS 20480
#define SMEM_BYTES (SMEM_ELEMS * 2)    // 40960 B

#define PSCALE 0.00390625f     // 2^-8: keeps p in fp16 range (exact scaling)

// static device scratch (no allocations allowed)
__device__ float g_Wh[(size_t)NN * OUTD];
__device__ float g_s1[NN];
__device__ float g_s2[NN];
__device__ __half g_WhT_hi[(size_t)OUTD * NN];  // [d][j]
__device__ __half g_WhT_lo[(size_t)OUTD * NN];
__device__ float g_part[(size_t)NSPLIT * NN * OUTD];
__device__ float g_lp[(size_t)NSPLIT * NN];

__device__ __forceinline__ uint32_t smem_u32(const void* p) {
    return (uint32_t)__cvta_generic_to_shared(p);
}
__device__ __forceinline__ void ldsm_x4(uint32_t& r0, uint32_t& r1, uint32_t& r2, uint32_t& r3, uint32_t a) {
    asm volatile("ldmatrix.sync.aligned.m8n8.x4.shared.b16 {%0,%1,%2,%3}, [%4];"
                 : "=r"(r0), "=r"(r1), "=r"(r2), "=r"(r3) : "r"(a));
}
__device__ __forceinline__ void mma_f16(float* c, const uint32_t* A, uint32_t b0, uint32_t b1) {
    asm volatile(
        "mma.sync.aligned.m16n8k16.row.col.f32.f16.f16.f32 "
        "{%0,%1,%2,%3}, {%4,%5,%6,%7}, {%8,%9}, {%0,%1,%2,%3};"
        : "+f"(c[0]), "+f"(c[1]), "+f"(c[2]), "+f"(c[3])
        : "r"(A[0]), "r"(A[1]), "r"(A[2]), "r"(A[3]), "r"(b0), "r"(b1));
}

// ---------------------------------------------------------------------------
// K1: Wh = x@W (fp32, coalesced); s1/s2 = Wh@a halves
// ---------------------------------------------------------------------------
__global__ __launch_bounds__(128) void k1_proj(const float* __restrict__ x,
                                               const float* __restrict__ W,
                                               const float* __restrict__ a) {
    __shared__ float W_sm[IND][OUTD];
    __shared__ float x_sm[32][33];

    const int t  = threadIdx.x;
    const int i0 = blockIdx.x * 32;
    const int dl = t & 15;
    const int rl = t >> 4;

    {
        const float4* src = (const float4*)W;
        float4* dst = (float4*)&W_sm[0][0];
#pragma unroll
        for (int q = 0; q < 16; ++q) dst[t + 128 * q] = src[t + 128 * q];
    }

    float acc[4][4];
#pragma unroll
    for (int rr = 0; rr < 4; ++rr)
#pragma unroll
        for (int dd = 0; dd < 4; ++dd) acc[rr][dd] = 0.f;

    for (int k0 = 0; k0 < IND; k0 += 32) {
        __syncthreads();
#pragma unroll
        for (int q = 0; q < 8; ++q) {
            int idx = t + 128 * q;
            int r = idx >> 5, kk = idx & 31;
            x_sm[r][kk] = x[(size_t)(i0 + r) * IND + k0 + kk];
        }
        __syncthreads();
#pragma unroll
        for (int kk = 0; kk < 32; ++kk) {
            float4 w = *(const float4*)&W_sm[k0 + kk][dl * 4];
#pragma unroll
            for (int rr = 0; rr < 4; ++rr) {
                float xv = x_sm[rl * 4 + rr][kk];
                acc[rr][0] += xv * w.x;
                acc[rr][1] += xv * w.y;
                acc[rr][2] += xv * w.z;
                acc[rr][3] += xv * w.w;
            }
        }
    }

    const float* a1 = a;
    const float* a2 = a + OUTD;
#pragma unroll
    for (int rr = 0; rr < 4; ++rr) {
        int row = i0 + rl * 4 + rr;
        *(float4*)&g_Wh[(size_t)row * OUTD + dl * 4] =
            make_float4(acc[rr][0], acc[rr][1], acc[rr][2], acc[rr][3]);
        float4 av1 = *(const float4*)&a1[dl * 4];
        float4 av2 = *(const float4*)&a2[dl * 4];
        float v1 = acc[rr][0] * av1.x + acc[rr][1] * av1.y + acc[rr][2] * av1.z + acc[rr][3] * av1.w;
        float v2 = acc[rr][0] * av2.x + acc[rr][1] * av2.y + acc[rr][2] * av2.z + acc[rr][3] * av2.w;
#pragma unroll
        for (int o = 8; o >= 1; o >>= 1) {
            v1 += __shfl_xor_sync(0xffffffffu, v1, o, 16);
            v2 += __shfl_xor_sync(0xffffffffu, v2, o, 16);
        }
        if (dl == 0) { g_s1[row] = v1; g_s2[row] = v2; }
    }
}

// ---------------------------------------------------------------------------
// K1b: transpose Wh -> WhT hi/lo fp16
// ---------------------------------------------------------------------------
__global__ __launch_bounds__(256) void k1b_transpose() {
    __shared__ float ts[64][68];
    const int t  = threadIdx.x;
    const int j0 = blockIdx.x * 64;

#pragma unroll
    for (int q = 0; q < 4; ++q) {
        int idx = t + 256 * q;
        int r = idx >> 4, c4 = (idx & 15) * 4;
        *(float4*)&ts[r][c4] = *(const float4*)&g_Wh[(size_t)(j0 + r) * OUTD + c4];
    }
    __syncthreads();

    const int d  = t >> 2;
    const int jq = (t & 3) * 16;
    uint32_t hi[8], lo[8];
#pragma unroll
    for (int u = 0; u < 8; ++u) {
        float v0 = ts[jq + 2 * u][d];
        float v1 = ts[jq + 2 * u + 1][d];
        __half h0 = __float2half_rn(v0);
        __half h1 = __float2half_rn(v1);
        __half2 hh = __halves2half2(h0, h1);
        hi[u] = *(uint32_t*)&hh;
        float r0 = v0 - __half2float(h0);
        float r1 = v1 - __half2float(h1);
        __half2 ll = __floats2half2_rn(r0, r1);
        lo[u] = *(uint32_t*)&ll;
    }
    __half* dh = g_WhT_hi + (size_t)d * NN + j0 + jq;
    __half* dl = g_WhT_lo + (size_t)d * NN + j0 + jq;
    *(uint4*)dh       = make_uint4(hi[0], hi[1], hi[2], hi[3]);
    *(uint4*)(dh + 8) = make_uint4(hi[4], hi[5], hi[6], hi[7]);
    *(uint4*)dl       = make_uint4(lo[0], lo[1], lo[2], lo[3]);
    *(uint4*)(dl + 8) = make_uint4(lo[4], lo[5], lo[6], lo[7]);
}

// ---------------------------------------------------------------------------
// K2: software-pipelined, 256 threads / 8 warps (warp owns m16), fp16 2-term.
// A = p*2^-8 fp16 single; B = W hi/lo fp16. Epilogue multiplies by 256.
// grid = (64, 6) = 384 blocks @ 3/SM single wave.
// ---------------------------------------------------------------------------
__global__ __launch_bounds__(256, 3) void k2_attn_mma(const int* __restrict__ adj) {
    extern __shared__ __half sm[];

    const int t     = threadIdx.x;
    const int wid   = t >> 5;
    const int lid   = t & 31;
    const int i0    = blockIdx.x * ITILE;
    const int split = blockIdx.y;

    const int base  = TOTTILES / NSPLIT;
    const int rem   = TOTTILES % NSPLIT;
    const int start = split * base + (split < rem ? split : rem);
    const int cnt   = base + (split < rem ? 1 : 0);
    const int js    = start * JT;

    // A-phase role: row = t>>1, 16-j half = (t&1)*16
    const int arow  = t >> 1;
    const int ahalf = (t & 1) * 16;
    const float s1v = g_s1[i0 + arow];
    const int* adjrow = adj + (size_t)(i0 + arow) * NN + js + ahalf;

    // B-phase role: row = t>>2, quarter = (t&3)*8
    const int bn = t >> 2, bk = (t & 3) * 8;
    const __half* bhp = g_WhT_hi + (size_t)bn * NN + js + bk;
    const __half* blp = g_WhT_lo + (size_t)bn * NN + js + bk;

    float lacc = 0.f;
    float c[8][4];
#pragma unroll
    for (int nt = 0; nt < 8; ++nt)
#pragma unroll
        for (int q = 0; q < 4; ++q) c[nt][q] = 0.f;

    auto build = [&](int tl, int b, const int4* pa) {
        const int j0 = tl * JT;
        // B tile: one uint4 hi + lo per thread
        *(uint4*)(sm + OFF_BH(b) + bn * BSTR + bk) = *(const uint4*)(bhp + j0);
        *(uint4*)(sm + OFF_BL(b) + bn * BSTR + bk) = *(const uint4*)(blp + j0);
        // A tile: 16 p values (scaled by 2^-8), fp16
        const float4* s4p = (const float4*)(g_s2 + js + j0 + ahalf);
        __half* Ah = sm + OFF_A(b) + arow * ASTR + ahalf;
#pragma unroll
        for (int k = 0; k < 2; ++k) {
            int4   aA = pa[2 * k], aB = pa[2 * k + 1];
            float4 sA = s4p[2 * k], sB = s4p[2 * k + 1];
            float p0, p1, p2, p3, p4, p5, p6, p7, e;
            e = s1v + sA.x; e = fmaxf(e, 0.2f * e); p0 = aA.x ? __expf(e) : 0.f;
            e = s1v + sA.y; e = fmaxf(e, 0.2f * e); p1 = aA.y ? __expf(e) : 0.f;
            e = s1v + sA.z; e = fmaxf(e, 0.2f * e); p2 = aA.z ? __expf(e) : 0.f;
            e = s1v + sA.w; e = fmaxf(e, 0.2f * e); p3 = aA.w ? __expf(e) : 0.f;
            e = s1v + sB.x; e = fmaxf(e, 0.2f * e); p4 = aB.x ? __expf(e) : 0.f;
            e = s1v + sB.y; e = fmaxf(e, 0.2f * e); p5 = aB.y ? __expf(e) : 0.f;
            e = s1v + sB.z; e = fmaxf(e, 0.2f * e); p6 = aB.z ? __expf(e) : 0.f;
            e = s1v + sB.w; e = fmaxf(e, 0.2f * e); p7 = aB.w ? __expf(e) : 0.f;
            lacc += ((p0 + p1) + (p2 + p3)) + ((p4 + p5) + (p6 + p7));

            __half2 h01 = __floats2half2_rn(p0 * PSCALE, p1 * PSCALE);
            __half2 h23 = __floats2half2_rn(p2 * PSCALE, p3 * PSCALE);
            __half2 h45 = __floats2half2_rn(p4 * PSCALE, p5 * PSCALE);
            __half2 h67 = __floats2half2_rn(p6 * PSCALE, p7 * PSCALE);
            *(uint4*)(Ah + k * 8) = make_uint4(*(uint32_t*)&h01, *(uint32_t*)&h23,
                                               *(uint32_t*)&h45, *(uint32_t*)&h67);
        }
    };

    // prologue: build tile 0 into buffer 0
    {
        int4 pa[4];
#pragma unroll
        for (int q = 0; q < 4; ++q) pa[q] = ((const int4*)adjrow)[q];
        build(0, 0, pa);
    }
    __syncthreads();

    const uint32_t ROWB = ASTR * 2;   // 80 B
    // B lane mapping for ldsm_x4 (R7-proven): 4 mats = 2 n-octets x 2 k-chunks
    const int bn_l = (lid & 7) + ((lid >> 4) << 3);
    const int bk_l = ((lid >> 3) & 1) * 8;

    for (int tile = 0; tile < cnt; ++tile) {
        const int cur = tile & 1, nb = cur ^ 1;

        int4 pa[4];
        if (tile + 1 < cnt) {
            const int4* src = (const int4*)(adjrow + (tile + 1) * JT);
#pragma unroll
            for (int q = 0; q < 4; ++q) pa[q] = src[q];
        }

        // ---- MMA on buffer cur: warp = m16 x n64 x k32, 2 terms
        const uint32_t a0  = smem_u32(sm + OFF_A(cur) + (wid * 16 + (lid & 15)) * ASTR + (lid >> 4) * 8);
        const uint32_t b0a = smem_u32(sm + OFF_BH(cur) + bn_l * BSTR + bk_l);
        const uint32_t b1a = smem_u32(sm + OFF_BL(cur) + bn_l * BSTR + bk_l);
#pragma unroll
        for (int kt = 0; kt < 2; ++kt) {
            uint32_t Ah[4];
            ldsm_x4(Ah[0], Ah[1], Ah[2], Ah[3], a0 + kt * 32);
#pragma unroll
            for (int np = 0; np < 4; ++np) {
                uint32_t bh0, bh1, bh2, bh3, bl0, bl1, bl2, bl3;
                ldsm_x4(bh0, bh1, bh2, bh3, b0a + (uint32_t)(np * 16) * ROWB + kt * 32);
                ldsm_x4(bl0, bl1, bl2, bl3, b1a + (uint32_t)(np * 16) * ROWB + kt * 32);
                mma_f16(c[2 * np],     Ah, bh0, bh1);
                mma_f16(c[2 * np],     Ah, bl0, bl1);
                mma_f16(c[2 * np + 1], Ah, bh2, bh3);
                mma_f16(c[2 * np + 1], Ah, bl2, bl3);
            }
        }

        // ---- build tile+1 into buffer nb
        if (tile + 1 < cnt) build(tile + 1, nb, pa);
        __syncthreads();
    }

    // l: the two half-row threads are adjacent lanes
    lacc += __shfl_xor_sync(0xffffffffu, lacc, 1);
    if ((t & 1) == 0) g_lp[(size_t)split * NN + i0 + arow] = lacc;

    // ---- epilogue: raw partials (undo 2^-8 scale)
    const int rbase = i0 + wid * 16 + (lid >> 2);
    const int cbase = 2 * (lid & 3);
#pragma unroll
    for (int nt = 0; nt < 8; ++nt) {
        const int col = nt * 8 + cbase;
        float* d0 = &g_part[((size_t)split * NN + rbase) * OUTD + col];
        float* d1 = &g_part[((size_t)split * NN + rbase + 8) * OUTD + col];
        *(float2*)d0 = make_float2(c[nt][0] * 256.f, c[nt][1] * 256.f);
        *(float2*)d1 = make_float2(c[nt][2] * 256.f, c[nt][3] * 256.f);
    }
}

// ---------------------------------------------------------------------------
// K3: reduce NSPLIT partials, normalize, ELU.
// ---------------------------------------------------------------------------
__global__ __launch_bounds__(128) void k3_reduce(float* __restrict__ out) {
    const int q   = blockIdx.x * 128 + threadIdx.x;
    const int row = q >> 4;
    const int c4  = (q & 15) * 4;

    float l = 0.f;
#pragma unroll
    for (int s = 0; s < NSPLIT; ++s) l += g_lp[(size_t)s * NN + row];
    const float inv = 1.0f / l;

    float4 acc = make_float4(0.f, 0.f, 0.f, 0.f);
#pragma unroll
    for (int s = 0; s < NSPLIT; ++s) {
        float4 v = *(const float4*)&g_part[((size_t)s * NN + row) * OUTD + c4];
        acc.x += v.x; acc.y += v.y; acc.z += v.z; acc.w += v.w;
    }
    acc.x *= inv; acc.y *= inv; acc.z *= inv; acc.w *= inv;
    acc.x = acc.x > 0.f ? acc.x : expm1f(acc.x);
    acc.y = acc.y > 0.f ? acc.y : expm1f(acc.y);
    acc.z = acc.z > 0.f ? acc.z : expm1f(acc.z);
    acc.w = acc.w > 0.f ? acc.w : expm1f(acc.w);
    *(float4*)&out[(size_t)row * OUTD + c4] = acc;
}

extern "C" void kernel_launch(void* const* d_in, const int* in_sizes, int n_in,
                              void* d_out, int out_size) {
    const float* x   = (const float*)d_in[0];
    const int*   adj = (const int*)d_in[1];
    const float* W   = (const float*)d_in[2];
    const float* a   = (const float*)d_in[3];
    float* out = (float*)d_out;

    cudaFuncSetAttribute(k2_attn_mma, cudaFuncAttributeMaxDynamicSharedMemorySize, SMEM_BYTES);

    k1_proj<<<256, 128>>>(x, W, a);
    k1b_transpose<<<NN / 64, 256>>>();
    k2_attn_mma<<<dim3(NN / ITILE, NSPLIT), 256, SMEM_BYTES>>>(adj);
    k3_reduce<<<(NN * OUTD / 4) / 128, 128>>>(out);
}